// round 6
// baseline (speedup 1.0000x reference)
#include <cuda_runtime.h>
#include <cuda_fp16.h>

#define BNUM 8
#define NPTS 30000
#define TOTALP (BNUM * NPTS)
#define OUTC 963   // 3 + 64 + 128 + 256 + 512

// NHWC fp16 scratch for the 4 feature pyramids
__device__ __half g_f0[(size_t)BNUM * 128 * 128 * 64];
__device__ __half g_f1[(size_t)BNUM * 64 * 64 * 128];
__device__ __half g_f2[(size_t)BNUM * 32 * 32 * 256];
__device__ __half g_f3[(size_t)BNUM * 16 * 16 * 512];

// ---------------------------------------------------------------------------
// NCHW fp32 -> NHWC fp16 transpose
// ---------------------------------------------------------------------------
__global__ void transpose_nchw_nhwc_h(const float* __restrict__ in,
                                      __half* __restrict__ out,
                                      int C, int HW) {
    __shared__ float tile[32][33];
    int b = blockIdx.z;
    const float* src = in + (size_t)b * C * HW;
    __half* dst = out + (size_t)b * C * HW;
    int hw0 = blockIdx.x * 32;
    int c0  = blockIdx.y * 32;

#pragma unroll
    for (int k = 0; k < 4; k++) {
        int c = c0 + threadIdx.y + k * 8;
        tile[threadIdx.y + k * 8][threadIdx.x] =
            src[(size_t)c * HW + hw0 + threadIdx.x];
    }
    __syncthreads();
#pragma unroll
    for (int k = 0; k < 4; k++) {
        int hw = hw0 + threadIdx.y + k * 8;
        dst[(size_t)hw * C + c0 + threadIdx.x] =
            __float2half(tile[threadIdx.x][threadIdx.y + k * 8]);
    }
}

// ---------------------------------------------------------------------------
// Gather helpers: accumulate 8 fp16 channels (one 16B LDG.128) per corner.
// ---------------------------------------------------------------------------
__device__ __forceinline__ void acc8(const __half* __restrict__ p, float w,
                                     float* __restrict__ r) {
    uint4 v = *(const uint4*)p;  // 8 halves
    __half2 h0 = *reinterpret_cast<const __half2*>(&v.x);
    __half2 h1 = *reinterpret_cast<const __half2*>(&v.y);
    __half2 h2 = *reinterpret_cast<const __half2*>(&v.z);
    __half2 h3 = *reinterpret_cast<const __half2*>(&v.w);
    float2 f0 = __half22float2(h0);
    float2 f1 = __half22float2(h1);
    float2 f2 = __half22float2(h2);
    float2 f3 = __half22float2(h3);
    r[0] = fmaf(f0.x, w, r[0]);
    r[1] = fmaf(f0.y, w, r[1]);
    r[2] = fmaf(f1.x, w, r[2]);
    r[3] = fmaf(f1.y, w, r[3]);
    r[4] = fmaf(f2.x, w, r[4]);
    r[5] = fmaf(f2.y, w, r[5]);
    r[6] = fmaf(f3.x, w, r[6]);
    r[7] = fmaf(f3.y, w, r[7]);
}

// Store 8 floats with warp-uniform alignment dispatch.
// sel = (address_in_floats) & 3, identical for all stores of this warp.
__device__ __forceinline__ void store8(float* __restrict__ dst,
                                       const float* __restrict__ r, int sel) {
    if (sel == 0) {
        // 16B aligned
        float4 a = make_float4(r[0], r[1], r[2], r[3]);
        float4 b = make_float4(r[4], r[5], r[6], r[7]);
        *(float4*)(dst)     = a;
        *(float4*)(dst + 4) = b;
    } else if (sel == 2) {
        // 8B aligned
        *(float2*)(dst)     = make_float2(r[0], r[1]);
        *(float2*)(dst + 2) = make_float2(r[2], r[3]);
        *(float2*)(dst + 4) = make_float2(r[4], r[5]);
        *(float2*)(dst + 6) = make_float2(r[6], r[7]);
    } else {
        // 4B aligned
#pragma unroll
        for (int i = 0; i < 8; i++) dst[i] = r[i];
    }
}

// ---------------------------------------------------------------------------
// Bilinear sample of one level, 8 channels per lane per iteration.
// ---------------------------------------------------------------------------
template <int C, int H, int W, int OFF>
__device__ __forceinline__ void sample_level(const __half* __restrict__ g,
                                             int b, int lane,
                                             float wn, float hn,
                                             float* __restrict__ orow,
                                             int sel) {
    float x = ((wn + 1.0f) * (float)W - 1.0f) * 0.5f;
    float y = ((hn + 1.0f) * (float)H - 1.0f) * 0.5f;
    float fx0 = floorf(x), fy0 = floorf(y);
    float tx = x - fx0, ty = y - fy0;
    int x0 = (int)fx0, y0 = (int)fy0;
    int x1 = x0 + 1,   y1 = y0 + 1;

    float wx0 = 1.0f - tx, wx1 = tx;
    float wy0 = 1.0f - ty, wy1 = ty;

    bool vx0 = (x0 >= 0) && (x0 < W);
    bool vx1 = (x1 >= 0) && (x1 < W);
    bool vy0 = (y0 >= 0) && (y0 < H);
    bool vy1 = (y1 >= 0) && (y1 < H);

    float w00 = (vx0 && vy0) ? wx0 * wy0 : 0.0f;
    float w10 = (vx1 && vy0) ? wx1 * wy0 : 0.0f;
    float w01 = (vx0 && vy1) ? wx0 * wy1 : 0.0f;
    float w11 = (vx1 && vy1) ? wx1 * wy1 : 0.0f;

    int x0c = min(max(x0, 0), W - 1), x1c = min(max(x1, 0), W - 1);
    int y0c = min(max(y0, 0), H - 1), y1c = min(max(y1, 0), H - 1);

    const __half* row0 = g + ((size_t)(b * H + y0c) * W) * C;
    const __half* row1 = g + ((size_t)(b * H + y1c) * W) * C;
    const __half* p00 = row0 + (size_t)x0c * C;
    const __half* p10 = row0 + (size_t)x1c * C;
    const __half* p01 = row1 + (size_t)x0c * C;
    const __half* p11 = row1 + (size_t)x1c * C;

#pragma unroll
    for (int c = lane * 8; c < C; c += 256) {
        float r[8] = {0.f, 0.f, 0.f, 0.f, 0.f, 0.f, 0.f, 0.f};
        acc8(p00 + c, w00, r);
        acc8(p10 + c, w10, r);
        acc8(p01 + c, w01, r);
        acc8(p11 + c, w11, r);
        store8(orow + OFF + c, r, sel);
    }
}

// ---------------------------------------------------------------------------
// Main kernel: 1 warp per point, 8 warps (256 thr) per block.
// ---------------------------------------------------------------------------
__global__ void project_sample_kernel(const float* __restrict__ resolution,
                                      const float* __restrict__ inputs,
                                      const float* __restrict__ camK,
                                      float* __restrict__ out,
                                      int total_pts) {
    int warp = (blockIdx.x * blockDim.x + threadIdx.x) >> 5;
    int lane = threadIdx.x & 31;
    if (warp >= total_pts) return;

    int b = warp / NPTS;

    const float cam_scale = 256.0f / 1920.0f;
    float hr0 = (resolution[0] - 1.0f) * 0.5f;
    float hr1 = (resolution[1] - 1.0f) * 0.5f;

    const float* K = camK + b * 9;
    float K00 = K[0] * cam_scale;
    float K01 = K[1] * cam_scale;
    float K02 = K[2] * cam_scale;
    float K11 = K[4] * cam_scale;
    float K12 = K[5] * cam_scale;

    const float* p = inputs + (size_t)warp * 3;
    float X = p[0];
    float Y = p[1];
    float Z = p[2] - 0.8f;  // MESH_POS

    float w = (-K00 * X - K01 * Y) / Z + K02 - hr0;
    float h = K11 * (Y / Z) + K12 - hr1;
    float wn = fminf(fmaxf(w / hr0, -1.0f), 1.0f);
    float hn = fminf(fmaxf(h / hr1, -1.0f), 1.0f);

    float* orow = out + (size_t)warp * OUTC;
    if (lane < 3) orow[lane] = p[lane];  // xyz, channels 0..2

    // Warp-uniform alignment selector of (orow + 3 + c), c % 8 == 0:
    // (963*warp + 3) mod 4 == (3*warp + 3) mod 4
    int sel = (3 * warp + 3) & 3;

    sample_level<64, 128, 128, 3>(g_f0, b, lane, wn, hn, orow, sel);
    sample_level<128, 64, 64, 67>(g_f1, b, lane, wn, hn, orow, sel);
    sample_level<256, 32, 32, 195>(g_f2, b, lane, wn, hn, orow, sel);
    sample_level<512, 16, 16, 451>(g_f3, b, lane, wn, hn, orow, sel);
}

extern "C" void kernel_launch(void* const* d_in, const int* in_sizes, int n_in,
                              void* d_out, int out_size) {
    const float* resolution = (const float*)d_in[0];
    const float* feat0 = (const float*)d_in[1];
    const float* feat1 = (const float*)d_in[2];
    const float* feat2 = (const float*)d_in[3];
    const float* feat3 = (const float*)d_in[4];
    const float* inputs = (const float*)d_in[5];
    const float* camK = (const float*)d_in[6];
    float* out = (float*)d_out;

    __half *pf0, *pf1, *pf2, *pf3;
    cudaGetSymbolAddress((void**)&pf0, g_f0);
    cudaGetSymbolAddress((void**)&pf1, g_f1);
    cudaGetSymbolAddress((void**)&pf2, g_f2);
    cudaGetSymbolAddress((void**)&pf3, g_f3);

    dim3 tb(32, 8);
    transpose_nchw_nhwc_h<<<dim3(128 * 128 / 32, 64 / 32, BNUM), tb>>>(feat0, pf0, 64, 128 * 128);
    transpose_nchw_nhwc_h<<<dim3(64 * 64 / 32, 128 / 32, BNUM), tb>>>(feat1, pf1, 128, 64 * 64);
    transpose_nchw_nhwc_h<<<dim3(32 * 32 / 32, 256 / 32, BNUM), tb>>>(feat2, pf2, 256, 32 * 32);
    transpose_nchw_nhwc_h<<<dim3(16 * 16 / 32, 512 / 32, BNUM), tb>>>(feat3, pf3, 512, 16 * 16);

    int total_pts = TOTALP;
    int warps_per_block = 8;  // 256 threads
    int blocks = (total_pts + warps_per_block - 1) / warps_per_block;
    project_sample_kernel<<<blocks, warps_per_block * 32>>>(resolution, inputs, camK, out, total_pts);
}

// round 7
// speedup vs baseline: 1.3380x; 1.3380x over previous
#include <cuda_runtime.h>
#include <cuda_fp16.h>

#define BNUM 8
#define NPTS 30000
#define TOTALP (BNUM * NPTS)
#define OUTC 963   // 3 + 64 + 128 + 256 + 512

// NHWC fp16 scratch for the 4 feature pyramids
__device__ __half g_f0[(size_t)BNUM * 128 * 128 * 64];
__device__ __half g_f1[(size_t)BNUM * 64 * 64 * 128];
__device__ __half g_f2[(size_t)BNUM * 32 * 32 * 256];
__device__ __half g_f3[(size_t)BNUM * 16 * 16 * 512];

// ---------------------------------------------------------------------------
// NCHW fp32 -> NHWC fp16 transpose
// ---------------------------------------------------------------------------
__global__ void transpose_nchw_nhwc_h(const float* __restrict__ in,
                                      __half* __restrict__ out,
                                      int C, int HW) {
    __shared__ float tile[32][33];
    int b = blockIdx.z;
    const float* src = in + (size_t)b * C * HW;
    __half* dst = out + (size_t)b * C * HW;
    int hw0 = blockIdx.x * 32;
    int c0  = blockIdx.y * 32;

#pragma unroll
    for (int k = 0; k < 4; k++) {
        int c = c0 + threadIdx.y + k * 8;
        tile[threadIdx.y + k * 8][threadIdx.x] =
            src[(size_t)c * HW + hw0 + threadIdx.x];
    }
    __syncthreads();
#pragma unroll
    for (int k = 0; k < 4; k++) {
        int hw = hw0 + threadIdx.y + k * 8;
        dst[(size_t)hw * C + c0 + threadIdx.x] =
            __float2half(tile[threadIdx.x][threadIdx.y + k * 8]);
    }
}

// ---------------------------------------------------------------------------
// Gather helper: accumulate 4 fp16 channels via read-only (ld.global.nc) path.
// ---------------------------------------------------------------------------
__device__ __forceinline__ void acc4(const __half* __restrict__ p, float w,
                                     float& r0, float& r1, float& r2, float& r3) {
    uint2 v = __ldg((const uint2*)p);   // LDG.E.NC.64
    __half2 h0 = *reinterpret_cast<const __half2*>(&v.x);
    __half2 h1 = *reinterpret_cast<const __half2*>(&v.y);
    float2 f0 = __half22float2(h0);
    float2 f1 = __half22float2(h1);
    r0 = fmaf(f0.x, w, r0);
    r1 = fmaf(f0.y, w, r1);
    r2 = fmaf(f1.x, w, r2);
    r3 = fmaf(f1.y, w, r3);
}

// ---------------------------------------------------------------------------
// Bilinear grid_sample of one level (NHWC fp16), 1 warp = 1 point.
// Output stores use streaming hint (.cs, evict-first) to avoid polluting L2:
// the 924MB output stream would otherwise evict the 63MB resident features.
// ---------------------------------------------------------------------------
template <int C, int H, int W, int OFF>
__device__ __forceinline__ void sample_level(const __half* __restrict__ g,
                                             int b, int lane,
                                             float wn, float hn,
                                             float* __restrict__ orow) {
    float x = ((wn + 1.0f) * (float)W - 1.0f) * 0.5f;
    float y = ((hn + 1.0f) * (float)H - 1.0f) * 0.5f;
    float fx0 = floorf(x), fy0 = floorf(y);
    float tx = x - fx0, ty = y - fy0;
    int x0 = (int)fx0, y0 = (int)fy0;
    int x1 = x0 + 1,   y1 = y0 + 1;

    float wx0 = 1.0f - tx, wx1 = tx;
    float wy0 = 1.0f - ty, wy1 = ty;

    bool vx0 = (x0 >= 0) && (x0 < W);
    bool vx1 = (x1 >= 0) && (x1 < W);
    bool vy0 = (y0 >= 0) && (y0 < H);
    bool vy1 = (y1 >= 0) && (y1 < H);

    float w00 = (vx0 && vy0) ? wx0 * wy0 : 0.0f;
    float w10 = (vx1 && vy0) ? wx1 * wy0 : 0.0f;
    float w01 = (vx0 && vy1) ? wx0 * wy1 : 0.0f;
    float w11 = (vx1 && vy1) ? wx1 * wy1 : 0.0f;

    int x0c = min(max(x0, 0), W - 1), x1c = min(max(x1, 0), W - 1);
    int y0c = min(max(y0, 0), H - 1), y1c = min(max(y1, 0), H - 1);

    const __half* row0 = g + ((size_t)(b * H + y0c) * W) * C;
    const __half* row1 = g + ((size_t)(b * H + y1c) * W) * C;
    const __half* p00 = row0 + (size_t)x0c * C;
    const __half* p10 = row0 + (size_t)x1c * C;
    const __half* p01 = row1 + (size_t)x0c * C;
    const __half* p11 = row1 + (size_t)x1c * C;

#pragma unroll
    for (int c = lane * 4; c < C; c += 128) {
        float r0 = 0.f, r1 = 0.f, r2 = 0.f, r3 = 0.f;
        acc4(p00 + c, w00, r0, r1, r2, r3);
        acc4(p10 + c, w10, r0, r1, r2, r3);
        acc4(p01 + c, w01, r0, r1, r2, r3);
        acc4(p11 + c, w11, r0, r1, r2, r3);
        float* o = orow + OFF + c;
        __stcs(o + 0, r0);   // STG.E.32.CS — evict-first, no L2 pollution
        __stcs(o + 1, r1);
        __stcs(o + 2, r2);
        __stcs(o + 3, r3);
    }
}

// ---------------------------------------------------------------------------
// Main kernel: 1 warp per point, 8 warps (256 thr) per block. Warp order ==
// point order, so consecutive warps write consecutive output rows (DRAM-
// friendly streaming writes).
// ---------------------------------------------------------------------------
__global__ void project_sample_kernel(const float* __restrict__ resolution,
                                      const float* __restrict__ inputs,
                                      const float* __restrict__ camK,
                                      float* __restrict__ out,
                                      int total_pts) {
    int warp = (blockIdx.x * blockDim.x + threadIdx.x) >> 5;
    int lane = threadIdx.x & 31;
    if (warp >= total_pts) return;

    int b = warp / NPTS;

    const float cam_scale = 256.0f / 1920.0f;
    float hr0 = (resolution[0] - 1.0f) * 0.5f;
    float hr1 = (resolution[1] - 1.0f) * 0.5f;

    const float* K = camK + b * 9;
    float K00 = K[0] * cam_scale;
    float K01 = K[1] * cam_scale;
    float K02 = K[2] * cam_scale;
    float K11 = K[4] * cam_scale;
    float K12 = K[5] * cam_scale;

    const float* p = inputs + (size_t)warp * 3;
    float X = p[0];
    float Y = p[1];
    float Z = p[2] - 0.8f;  // MESH_POS

    float w = (-K00 * X - K01 * Y) / Z + K02 - hr0;
    float h = K11 * (Y / Z) + K12 - hr1;
    float wn = fminf(fmaxf(w / hr0, -1.0f), 1.0f);
    float hn = fminf(fmaxf(h / hr1, -1.0f), 1.0f);

    float* orow = out + (size_t)warp * OUTC;
    if (lane < 3) __stcs(orow + lane, p[lane]);  // xyz, channels 0..2

    sample_level<64, 128, 128, 3>(g_f0, b, lane, wn, hn, orow);
    sample_level<128, 64, 64, 67>(g_f1, b, lane, wn, hn, orow);
    sample_level<256, 32, 32, 195>(g_f2, b, lane, wn, hn, orow);
    sample_level<512, 16, 16, 451>(g_f3, b, lane, wn, hn, orow);
}

extern "C" void kernel_launch(void* const* d_in, const int* in_sizes, int n_in,
                              void* d_out, int out_size) {
    const float* resolution = (const float*)d_in[0];
    const float* feat0 = (const float*)d_in[1];
    const float* feat1 = (const float*)d_in[2];
    const float* feat2 = (const float*)d_in[3];
    const float* feat3 = (const float*)d_in[4];
    const float* inputs = (const float*)d_in[5];
    const float* camK = (const float*)d_in[6];
    float* out = (float*)d_out;

    __half *pf0, *pf1, *pf2, *pf3;
    cudaGetSymbolAddress((void**)&pf0, g_f0);
    cudaGetSymbolAddress((void**)&pf1, g_f1);
    cudaGetSymbolAddress((void**)&pf2, g_f2);
    cudaGetSymbolAddress((void**)&pf3, g_f3);

    dim3 tb(32, 8);
    transpose_nchw_nhwc_h<<<dim3(128 * 128 / 32, 64 / 32, BNUM), tb>>>(feat0, pf0, 64, 128 * 128);
    transpose_nchw_nhwc_h<<<dim3(64 * 64 / 32, 128 / 32, BNUM), tb>>>(feat1, pf1, 128, 64 * 64);
    transpose_nchw_nhwc_h<<<dim3(32 * 32 / 32, 256 / 32, BNUM), tb>>>(feat2, pf2, 256, 32 * 32);
    transpose_nchw_nhwc_h<<<dim3(16 * 16 / 32, 512 / 32, BNUM), tb>>>(feat3, pf3, 512, 16 * 16);

    int total_pts = TOTALP;
    int warps_per_block = 8;  // 256 threads
    int blocks = (total_pts + warps_per_block - 1) / warps_per_block;
    project_sample_kernel<<<blocks, warps_per_block * 32>>>(resolution, inputs, camK, out, total_pts);
}